// round 2
// baseline (speedup 1.0000x reference)
#include <cuda_runtime.h>
#include <math.h>

#define NN 100000
#define NE 1000000
#define DIM 64
#define KSTEPS 10

// ---------------- static scratch (no allocations allowed) ----------------
__device__ int   g_out_deg[NN];
__device__ int   g_in_deg[NN];
__device__ float g_src_norm[NN];
__device__ float g_dst_norm[NN];
__device__ int   g_row_ptr[NN + 1];
__device__ int   g_fill[NN];
__device__ int   g_col[NE];     // src node ids grouped by dst (CSR)
__device__ float g_ew[NE];      // folded edge weight src_norm[s]*dst_norm[d]
__device__ float g_h0[(size_t)NN * DIM];
__device__ float g_h1[(size_t)NN * DIM];
__device__ int   g_blk[256];    // block sums for the scan
__device__ int   g_is64;        // 1 if edge indices are int64, 0 if int32

// index accessor: buffers are viewed as int32 words
__device__ __forceinline__ int edge_at(const int* __restrict__ b, int i, int is64) {
    return b[is64 ? (i << 1) : i];
}

// ---------------- dtype detection + CSR build ----------------
__global__ void k_zero(int n) {
    int i = blockIdx.x * blockDim.x + threadIdx.x;
    if (i < n) { g_out_deg[i] = 0; g_in_deg[i] = 0; g_fill[i] = 0; }
    if (i == 0) g_is64 = 1;   // assume int64 until a nonzero high word disproves it
}

__global__ void k_detect(const int* __restrict__ src32) {
    // If int64: words at odd positions are high halves of values < 2^31 -> all 0.
    // If int32: they are random node ids, almost surely nonzero somewhere.
    int i = threadIdx.x;                  // 0..1023, reads first 8KB (safe for both widths)
    if (src32[2 * i + 1] != 0) g_is64 = 0;
}

__global__ void k_count(const int* __restrict__ src,
                        const int* __restrict__ dst, int e) {
    int i = blockIdx.x * blockDim.x + threadIdx.x;
    int is64 = g_is64;
    if (i < e) {
        atomicAdd(&g_out_deg[edge_at(src, i, is64)], 1);
        atomicAdd(&g_in_deg[edge_at(dst, i, is64)], 1);
    }
}

__global__ void k_norm(int n) {
    int i = blockIdx.x * blockDim.x + threadIdx.x;
    if (i < n) {
        g_src_norm[i] = rsqrtf(fmaxf((float)g_out_deg[i], 1.0f));
        g_dst_norm[i] = rsqrtf(fmaxf((float)g_in_deg[i], 1.0f));
    }
}

// exclusive scan of g_in_deg -> g_row_ptr (3-kernel hierarchical)
__global__ void k_scan1(int n) {
    __shared__ int sh[1024];
    int gid = blockIdx.x * 1024 + threadIdx.x;
    int v = (gid < n) ? g_in_deg[gid] : 0;
    sh[threadIdx.x] = v;
    __syncthreads();
#pragma unroll
    for (int off = 1; off < 1024; off <<= 1) {
        int t = (threadIdx.x >= (unsigned)off) ? sh[threadIdx.x - off] : 0;
        __syncthreads();
        sh[threadIdx.x] += t;
        __syncthreads();
    }
    if (gid < n) g_row_ptr[gid] = sh[threadIdx.x] - v;   // exclusive
    if (threadIdx.x == 1023) g_blk[blockIdx.x] = sh[1023];
}

__global__ void k_scan2(int nblk, int etotal, int n) {
    if (threadIdx.x == 0 && blockIdx.x == 0) {
        int run = 0;
        for (int b = 0; b < nblk; b++) { int t = g_blk[b]; g_blk[b] = run; run += t; }
        g_row_ptr[n] = etotal;
    }
}

__global__ void k_scan3(int n) {
    int gid = blockIdx.x * 1024 + threadIdx.x;
    if (gid < n) g_row_ptr[gid] += g_blk[blockIdx.x];
}

__global__ void k_fill(const int* __restrict__ src,
                       const int* __restrict__ dst, int e) {
    int i = blockIdx.x * blockDim.x + threadIdx.x;
    int is64 = g_is64;
    if (i < e) {
        int s = edge_at(src, i, is64);
        int d = edge_at(dst, i, is64);
        int pos = g_row_ptr[d] + atomicAdd(&g_fill[d], 1);
        g_col[pos] = s;
        g_ew[pos]  = g_src_norm[s] * g_dst_norm[d];
    }
}

// ---------------- propagation ----------------
__global__ void k_init_out(const float* __restrict__ feat,
                           float* __restrict__ out, float w0, int nd) {
    int i = blockIdx.x * blockDim.x + threadIdx.x;
    if (i < nd) out[i] = w0 * feat[i];
}

// warp per dst node; each lane owns 2 of the 64 columns (float2 slice).
// hout[v] = sum_e ew[e]*hin[col[e]] ; out[v] += wk*hout[v]
__global__ void __launch_bounds__(256)
k_spmm(const float* __restrict__ hin, float* __restrict__ hout,
       float* __restrict__ out, float wk, int n) {
    int t = blockIdx.x * blockDim.x + threadIdx.x;
    int node = t >> 5;
    int lane = t & 31;
    if (node >= n) return;
    int beg = g_row_ptr[node];
    int end = g_row_ptr[node + 1];

    float ax = 0.0f, ay = 0.0f;
    int e = beg;
    // 4-way unroll: four independent 256B gathers in flight per warp
    for (; e + 4 <= end; e += 4) {
        int   s0 = g_col[e],     s1 = g_col[e + 1];
        int   s2 = g_col[e + 2], s3 = g_col[e + 3];
        float w0 = g_ew[e],      w1 = g_ew[e + 1];
        float w2 = g_ew[e + 2],  w3 = g_ew[e + 3];
        float2 v0 = *(const float2*)(hin + (size_t)s0 * DIM + lane * 2);
        float2 v1 = *(const float2*)(hin + (size_t)s1 * DIM + lane * 2);
        float2 v2 = *(const float2*)(hin + (size_t)s2 * DIM + lane * 2);
        float2 v3 = *(const float2*)(hin + (size_t)s3 * DIM + lane * 2);
        ax += w0 * v0.x; ay += w0 * v0.y;
        ax += w1 * v1.x; ay += w1 * v1.y;
        ax += w2 * v2.x; ay += w2 * v2.y;
        ax += w3 * v3.x; ay += w3 * v3.y;
    }
    for (; e < end; e++) {
        int   s = g_col[e];
        float w = g_ew[e];
        float2 v = *(const float2*)(hin + (size_t)s * DIM + lane * 2);
        ax += w * v.x; ay += w * v.y;
    }

    size_t o = (size_t)node * DIM + lane * 2;
    *(float2*)(hout + o) = make_float2(ax, ay);
    float2 ov = *(const float2*)(out + o);
    ov.x += wk * ax; ov.y += wk * ay;
    *(float2*)(out + o) = ov;
}

// ---------------- launch ----------------
extern "C" void kernel_launch(void* const* d_in, const int* in_sizes, int n_in,
                              void* d_out, int out_size) {
    const float* feat  = (const float*)d_in[0];
    const int*   src32 = (const int*)d_in[1];
    const int*   dst32 = (const int*)d_in[2];
    float* out = (float*)d_out;

    int n = in_sizes[0] / DIM;   // 100000
    int e = in_sizes[1];         // 1000000

    void *p0, *p1;
    cudaGetSymbolAddress(&p0, g_h0);
    cudaGetSymbolAddress(&p1, g_h1);
    float* h0 = (float*)p0;
    float* h1 = (float*)p1;

    // log weights: logs[j] = log(BETA + 1 + j), j = 0..K
    double logs[KSTEPS + 1]; double denom = 0.0;
    for (int j = 0; j <= KSTEPS; j++) { logs[j] = log(2.0 + 1.0 + (double)j); denom += logs[j]; }

    int nb_n = (n + 255) / 256;
    int nb_e = (e + 255) / 256;
    int nblk = (n + 1023) / 1024;

    k_zero  <<<nb_n, 256>>>(n);
    k_detect<<<1, 1024>>>(src32);
    k_count <<<nb_e, 256>>>(src32, dst32, e);
    k_norm  <<<nb_n, 256>>>(n);
    k_scan1 <<<nblk, 1024>>>(n);
    k_scan2 <<<1, 32>>>(nblk, e, n);
    k_scan3 <<<nblk, 1024>>>(n);
    k_fill  <<<nb_e, 256>>>(src32, dst32, e);

    int nd = n * DIM;
    k_init_out<<<(nd + 255) / 256, 256>>>(feat, out, (float)(logs[0] / denom), nd);

    int nb_s = (n * 32 + 255) / 256;
    const float* hin = feat;
    float* hout = h0;
    for (int s = 0; s < KSTEPS; s++) {
        k_spmm<<<nb_s, 256>>>(hin, hout, out, (float)(logs[s + 1] / denom), n);
        hin = hout;
        hout = (hout == h0) ? h1 : h0;
    }
}

// round 3
// speedup vs baseline: 1.2070x; 1.2070x over previous
#include <cuda_runtime.h>
#include <cuda_fp16.h>
#include <math.h>

#define NN 100000
#define NE 1000000
#define DIM 64
#define KSTEPS 10

// ---------------- static scratch (no allocations allowed) ----------------
__device__ int     g_out_deg[NN];
__device__ int     g_in_deg[NN];
__device__ float   g_src_norm[NN];
__device__ float   g_dst_norm[NN];
__device__ int     g_row_ptr[NN + 1];
__device__ int     g_fill[NN];
__device__ uint2   g_edge[NE];              // .x = src id, .y = bits(src_norm*dst_norm)
__device__ __half2 g_y0[(size_t)NN * (DIM / 2)];
__device__ __half2 g_y1[(size_t)NN * (DIM / 2)];
__device__ int     g_blk[256];              // block sums for the scan
__device__ int     g_is64;                  // 1 if edge indices are int64, 0 if int32

// index accessor: buffers are viewed as int32 words
__device__ __forceinline__ int edge_at(const int* __restrict__ b, int i, int is64) {
    return b[is64 ? (i << 1) : i];
}

// ---------------- dtype detection + CSR build ----------------
__global__ void k_zero(int n) {
    int i = blockIdx.x * blockDim.x + threadIdx.x;
    if (i < n) { g_out_deg[i] = 0; g_in_deg[i] = 0; g_fill[i] = 0; }
    if (i == 0) g_is64 = 1;   // assume int64 until a nonzero high word disproves it
}

__global__ void k_detect(const int* __restrict__ src32) {
    // If int64: odd 32-bit words are high halves of values < 2^31 -> all 0.
    // If int32: they are random node ids, almost surely nonzero somewhere.
    int i = threadIdx.x;                  // 0..1023
    if (src32[2 * i + 1] != 0) g_is64 = 0;
}

__global__ void k_count(const int* __restrict__ src,
                        const int* __restrict__ dst, int e) {
    int i = blockIdx.x * blockDim.x + threadIdx.x;
    int is64 = g_is64;
    if (i < e) {
        atomicAdd(&g_out_deg[edge_at(src, i, is64)], 1);
        atomicAdd(&g_in_deg[edge_at(dst, i, is64)], 1);
    }
}

__global__ void k_norm(int n) {
    int i = blockIdx.x * blockDim.x + threadIdx.x;
    if (i < n) {
        g_src_norm[i] = rsqrtf(fmaxf((float)g_out_deg[i], 1.0f));
        g_dst_norm[i] = rsqrtf(fmaxf((float)g_in_deg[i], 1.0f));
    }
}

// exclusive scan of g_in_deg -> g_row_ptr (3-kernel hierarchical)
__global__ void k_scan1(int n) {
    __shared__ int sh[1024];
    int gid = blockIdx.x * 1024 + threadIdx.x;
    int v = (gid < n) ? g_in_deg[gid] : 0;
    sh[threadIdx.x] = v;
    __syncthreads();
#pragma unroll
    for (int off = 1; off < 1024; off <<= 1) {
        int t = (threadIdx.x >= (unsigned)off) ? sh[threadIdx.x - off] : 0;
        __syncthreads();
        sh[threadIdx.x] += t;
        __syncthreads();
    }
    if (gid < n) g_row_ptr[gid] = sh[threadIdx.x] - v;   // exclusive
    if (threadIdx.x == 1023) g_blk[blockIdx.x] = sh[1023];
}

__global__ void k_scan2(int nblk, int etotal, int n) {
    if (threadIdx.x == 0 && blockIdx.x == 0) {
        int run = 0;
        for (int b = 0; b < nblk; b++) { int t = g_blk[b]; g_blk[b] = run; run += t; }
        g_row_ptr[n] = etotal;
    }
}

__global__ void k_scan3(int n) {
    int gid = blockIdx.x * 1024 + threadIdx.x;
    if (gid < n) g_row_ptr[gid] += g_blk[blockIdx.x];
}

__global__ void k_fill(const int* __restrict__ src,
                       const int* __restrict__ dst, int e) {
    int i = blockIdx.x * blockDim.x + threadIdx.x;
    int is64 = g_is64;
    if (i < e) {
        int s = edge_at(src, i, is64);
        int d = edge_at(dst, i, is64);
        int pos = g_row_ptr[d] + atomicAdd(&g_fill[d], 1);
        float w = g_src_norm[s] * g_dst_norm[d];
        g_edge[pos] = make_uint2((unsigned)s, __float_as_uint(w));
    }
}

// ---------------- Horner propagation ----------------
// y_K = w_K * feat ; then y <- w_k * feat + A_hat * y for k = K-1 .. 0.
// Final (k=0) iteration writes fp32 out; intermediates stored fp16.

__global__ void k_init_y(const float* __restrict__ feat,
                         __half2* __restrict__ y, float wK, int n32) {
    int i = blockIdx.x * blockDim.x + threadIdx.x;
    if (i < n32) {
        float2 f = *(const float2*)(feat + (size_t)i * 2);
        y[i] = __floats2half2_rn(wK * f.x, wK * f.y);
    }
}

// warp per dst node; lane owns 2 of 64 columns (one half2).
__global__ void __launch_bounds__(256)
k_step(const __half2* __restrict__ yin, __half2* __restrict__ yout,
       const float* __restrict__ feat, float* __restrict__ out,
       float wk, int n, int last) {
    int t = blockIdx.x * blockDim.x + threadIdx.x;
    int node = t >> 5;
    int lane = t & 31;
    if (node >= n) return;
    int beg = g_row_ptr[node];
    int end = g_row_ptr[node + 1];

    float ax = 0.0f, ay = 0.0f;
    int e = beg;
    // 4-way unroll: four independent 128B gathers in flight per warp
    for (; e + 4 <= end; e += 4) {
        uint2 e0 = g_edge[e],     e1 = g_edge[e + 1];
        uint2 e2 = g_edge[e + 2], e3 = g_edge[e + 3];
        float2 v0 = __half22float2(yin[(size_t)e0.x * 32 + lane]);
        float2 v1 = __half22float2(yin[(size_t)e1.x * 32 + lane]);
        float2 v2 = __half22float2(yin[(size_t)e2.x * 32 + lane]);
        float2 v3 = __half22float2(yin[(size_t)e3.x * 32 + lane]);
        float w0 = __uint_as_float(e0.y), w1 = __uint_as_float(e1.y);
        float w2 = __uint_as_float(e2.y), w3 = __uint_as_float(e3.y);
        ax += w0 * v0.x; ay += w0 * v0.y;
        ax += w1 * v1.x; ay += w1 * v1.y;
        ax += w2 * v2.x; ay += w2 * v2.y;
        ax += w3 * v3.x; ay += w3 * v3.y;
    }
    for (; e < end; e++) {
        uint2 ed = g_edge[e];
        float2 v = __half22float2(yin[(size_t)ed.x * 32 + lane]);
        float w = __uint_as_float(ed.y);
        ax += w * v.x; ay += w * v.y;
    }

    float2 f = *(const float2*)(feat + (size_t)node * DIM + lane * 2);
    float rx = wk * f.x + ax;
    float ry = wk * f.y + ay;

    if (last) {
        *(float2*)(out + (size_t)node * DIM + lane * 2) = make_float2(rx, ry);
    } else {
        yout[(size_t)node * 32 + lane] = __floats2half2_rn(rx, ry);
    }
}

// ---------------- launch ----------------
extern "C" void kernel_launch(void* const* d_in, const int* in_sizes, int n_in,
                              void* d_out, int out_size) {
    const float* feat  = (const float*)d_in[0];
    const int*   src32 = (const int*)d_in[1];
    const int*   dst32 = (const int*)d_in[2];
    float* out = (float*)d_out;

    int n = in_sizes[0] / DIM;   // 100000
    int e = in_sizes[1];         // 1000000

    void *p0, *p1;
    cudaGetSymbolAddress(&p0, g_y0);
    cudaGetSymbolAddress(&p1, g_y1);
    __half2* y0 = (__half2*)p0;
    __half2* y1 = (__half2*)p1;

    // log weights: w[j] = log(BETA + 1 + j) / denom, j = 0..K  (BETA = 2)
    double logs[KSTEPS + 1]; double denom = 0.0;
    for (int j = 0; j <= KSTEPS; j++) { logs[j] = log(3.0 + (double)j); denom += logs[j]; }

    int nb_n = (n + 255) / 256;
    int nb_e = (e + 255) / 256;
    int nblk = (n + 1023) / 1024;

    k_zero  <<<nb_n, 256>>>(n);
    k_detect<<<1, 1024>>>(src32);
    k_count <<<nb_e, 256>>>(src32, dst32, e);
    k_norm  <<<nb_n, 256>>>(n);
    k_scan1 <<<nblk, 1024>>>(n);
    k_scan2 <<<1, 32>>>(nblk, e, n);
    k_scan3 <<<nblk, 1024>>>(n);
    k_fill  <<<nb_e, 256>>>(src32, dst32, e);

    int n32 = n * 32;
    k_init_y<<<(n32 + 255) / 256, 256>>>(feat, y0, (float)(logs[KSTEPS] / denom), n32);

    int nb_s = (n32 + 255) / 256;
    __half2* yin = y0;
    __half2* yout = y1;
    for (int k = KSTEPS - 1; k >= 0; k--) {
        int last = (k == 0);
        k_step<<<nb_s, 256>>>(yin, yout, feat, out,
                              (float)(logs[k] / denom), n, last);
        __half2* tmp = yin; yin = yout; yout = tmp;
    }
}